// round 5
// baseline (speedup 1.0000x reference)
#include <cuda_runtime.h>
#include <cstdint>

#define HIDDEN   5120
#define NEXP     160
#define NGROUP   8
#define EPG      20
#define TOPK     6

#define BM       128
#define BK       16
#define NTHREADS 512
#define KTILES   (HIDDEN / BK)   // 320
#define LSTR     161

#define APSTR    130             // A-dup stride per kk row, in 8B pairs
#define BSTR     164             // B stride per kk row, in floats
#define A_BYTES  (BK * APSTR * 8)            // 16640
#define B_BYTES  (BK * BSTR * 4)             // 10496
#define BUF_BYTES (A_BYTES + B_BYTES)        // 27136 (16B aligned)

#define SMEM_BYTES (BM * LSTR * 4)   // 82432 >= 2*BUF_BYTES (54272)

#define NEG_INF (-__int_as_float(0x7f800000))

// ---- packed f32x2 helpers (sm_103a) ----
__device__ __forceinline__ void fma2(unsigned long long& d,
                                     unsigned long long a,
                                     unsigned long long b) {
    asm("fma.rn.f32x2 %0, %1, %2, %0;" : "+l"(d) : "l"(a), "l"(b));
}
__device__ __forceinline__ unsigned long long pack2(float x) {
    unsigned long long r;
    unsigned u = __float_as_uint(x);
    asm("mov.b64 %0, {%1, %1};" : "=l"(r) : "r"(u));
    return r;
}
__device__ __forceinline__ void unpack2(unsigned long long v, float& lo, float& hi) {
    unsigned a, b;
    asm("mov.b64 {%0, %1}, %2;" : "=r"(a), "=r"(b) : "l"(v));
    lo = __uint_as_float(a);
    hi = __uint_as_float(b);
}

extern "C" __global__ void __launch_bounds__(NTHREADS, 1)
moe_gate_kernel(const float* __restrict__ X,   // [T, HIDDEN]
                const float* __restrict__ W,   // [NEXP, HIDDEN]
                float* __restrict__ out,       // [T*6 idx][T*6 weights]
                int T)
{
    extern __shared__ float smem[];
    float* logits = smem;   // reused after GEMM

    const int tid  = threadIdx.x;
    const int tm   = tid >> 4;      // 0..31 -> 4 token rows each
    const int tn   = tid & 15;      // 0..15 -> 10 expert cols each
    const int row0 = blockIdx.x * BM;

    // accumulators: 4 m-rows x 5 n-pairs (f32x2)
    unsigned long long acc[4][5];
#pragma unroll
    for (int i = 0; i < 4; i++)
#pragma unroll
        for (int j = 0; j < 5; j++) acc[i][j] = 0ull;

    // ---- global load mapping ----
    const int ar = tid >> 2, aq = tid & 3;       // A: 512 float4
    const int br0 = tid >> 2, bq0 = tid & 3;     // B: 640 float4
    const int bi1 = tid + 512;
    const int br1 = bi1 >> 2, bq1 = bi1 & 3;
    const bool bpred = (bi1 < 640);

    const float* Arow  = X + (size_t)(row0 + ar) * HIDDEN + aq * 4;
    const float* Brow0 = W + (size_t)br0 * HIDDEN + bq0 * 4;
    const float* Brow1 = W + (size_t)br1 * HIDDEN + bq1 * 4;

    float4 aS, bS0, bS1;
    bS1 = make_float4(0.f, 0.f, 0.f, 0.f);

    aS  = *(const float4*)(Arow);
    bS0 = *(const float4*)(Brow0);
    if (bpred) bS1 = *(const float4*)(Brow1);

    for (int kt = 0; kt < KTILES; ++kt) {
        char* buf = (char*)smem + (kt & 1) * BUF_BYTES;
        unsigned long long* Ad = (unsigned long long*)buf;       // dup pairs
        float* Bs = (float*)(buf + A_BYTES);

        // ---- stage: A duplicated pairs, B plain floats ----
        Ad[(aq * 4 + 0) * APSTR + ar] = pack2(aS.x);
        Ad[(aq * 4 + 1) * APSTR + ar] = pack2(aS.y);
        Ad[(aq * 4 + 2) * APSTR + ar] = pack2(aS.z);
        Ad[(aq * 4 + 3) * APSTR + ar] = pack2(aS.w);

        Bs[(bq0 * 4 + 0) * BSTR + br0] = bS0.x;
        Bs[(bq0 * 4 + 1) * BSTR + br0] = bS0.y;
        Bs[(bq0 * 4 + 2) * BSTR + br0] = bS0.z;
        Bs[(bq0 * 4 + 3) * BSTR + br0] = bS0.w;
        if (bpred) {
            Bs[(bq1 * 4 + 0) * BSTR + br1] = bS1.x;
            Bs[(bq1 * 4 + 1) * BSTR + br1] = bS1.y;
            Bs[(bq1 * 4 + 2) * BSTR + br1] = bS1.z;
            Bs[(bq1 * 4 + 3) * BSTR + br1] = bS1.w;
        }
        __syncthreads();

        // ---- prefetch next tile (global) ----
        if (kt + 1 < KTILES) {
            const int k0 = (kt + 1) * BK;
            aS  = *(const float4*)(Arow + k0);
            bS0 = *(const float4*)(Brow0 + k0);
            if (bpred) bS1 = *(const float4*)(Brow1 + k0);
        }

        // ---- software-pipelined fragment loop over 16 k-steps ----
        const unsigned long long* Abase = Ad + tm * 4;
        const char* Bbase = (const char*)Bs + tn * 40;

        ulonglong2 a0c = *(const ulonglong2*)(Abase);
        ulonglong2 a1c = *(const ulonglong2*)(Abase + 2);
        unsigned long long b0c, b1c, b2c, b3c, b4c;
        {
            const unsigned long long* bp = (const unsigned long long*)Bbase;
            b0c = bp[0]; b1c = bp[1]; b2c = bp[2]; b3c = bp[3]; b4c = bp[4];
        }

#pragma unroll
        for (int kk = 0; kk < BK; ++kk) {
            ulonglong2 a0n, a1n;
            unsigned long long b0n, b1n, b2n, b3n, b4n;
            if (kk + 1 < BK) {
                const unsigned long long* ap = Abase + (kk + 1) * APSTR;
                a0n = *(const ulonglong2*)(ap);
                a1n = *(const ulonglong2*)(ap + 2);
                const unsigned long long* bp =
                    (const unsigned long long*)(Bbase + (size_t)(kk + 1) * (BSTR * 4));
                b0n = bp[0]; b1n = bp[1]; b2n = bp[2]; b3n = bp[3]; b4n = bp[4];
            }

            const unsigned long long pa0 = a0c.x, pa1 = a0c.y;
            const unsigned long long pa2 = a1c.x, pa3 = a1c.y;

            fma2(acc[0][0], pa0, b0c); fma2(acc[0][1], pa0, b1c);
            fma2(acc[0][2], pa0, b2c); fma2(acc[0][3], pa0, b3c);
            fma2(acc[0][4], pa0, b4c);
            fma2(acc[1][0], pa1, b0c); fma2(acc[1][1], pa1, b1c);
            fma2(acc[1][2], pa1, b2c); fma2(acc[1][3], pa1, b3c);
            fma2(acc[1][4], pa1, b4c);
            fma2(acc[2][0], pa2, b0c); fma2(acc[2][1], pa2, b1c);
            fma2(acc[2][2], pa2, b2c); fma2(acc[2][3], pa2, b3c);
            fma2(acc[2][4], pa2, b4c);
            fma2(acc[3][0], pa3, b0c); fma2(acc[3][1], pa3, b1c);
            fma2(acc[3][2], pa3, b2c); fma2(acc[3][3], pa3, b3c);
            fma2(acc[3][4], pa3, b4c);

            if (kk + 1 < BK) {
                a0c = a0n; a1c = a1n;
                b0c = b0n; b1c = b1n; b2c = b2n; b3c = b3n; b4c = b4n;
            }
        }
    }

    // ---- epilogue: logits to smem ----
    __syncthreads();
#pragma unroll
    for (int i = 0; i < 4; i++) {
        const int r = tm * 4 + i;
#pragma unroll
        for (int j = 0; j < 5; j++) {
            float lo, hi;
            unpack2(acc[i][j], lo, hi);
            logits[r * LSTR + tn * 10 + 2 * j]     = lo;
            logits[r * LSTR + tn * 10 + 2 * j + 1] = hi;
        }
    }
    __syncthreads();

    // ---- gating: one thread per token (verified code) ----
    if (tid < BM) {
        const int t = row0 + tid;
        if (t < T) {
            const float* row = logits + tid * LSTR;

            float gmax[NGROUP];
            float m = NEG_INF;
#pragma unroll
            for (int g = 0; g < NGROUP; g++) {
                float gm = NEG_INF;
#pragma unroll
                for (int j = 0; j < EPG; j++)
                    gm = fmaxf(gm, row[g * EPG + j]);
                gmax[g] = gm;
                m = fmaxf(m, gm);
            }

            float v0 = NEG_INF, v1 = NEG_INF, v2 = NEG_INF;
            int g0 = 0, g1 = 0, g2 = 0;
#pragma unroll
            for (int g = 0; g < NGROUP; g++) {
                const float v = gmax[g];
                if (v > v0)      { v2 = v1; g2 = g1; v1 = v0; g1 = g0; v0 = v; g0 = g; }
                else if (v > v1) { v2 = v1; g2 = g1; v1 = v;  g1 = g; }
                else if (v > v2) { v2 = v;  g2 = g; }
            }
            const unsigned gm_mask = (1u << g0) | (1u << g1) | (1u << g2);

            float tv0 = NEG_INF, tv1 = NEG_INF, tv2 = NEG_INF;
            float tv3 = NEG_INF, tv4 = NEG_INF, tv5 = NEG_INF;
            int ti0 = -1, ti1 = -1, ti2 = -1, ti3 = -1, ti4 = -1, ti5 = -1;
#pragma unroll 1
            for (int g = 0; g < NGROUP; g++) {
                if (!((gm_mask >> g) & 1u)) continue;
#pragma unroll 1
                for (int j = 0; j < EPG; j++) {
                    const int e = g * EPG + j;
                    const float v = row[e];
                    if (v > tv5) {
                        if (v > tv4) { tv5 = tv4; ti5 = ti4;
                            if (v > tv3) { tv4 = tv3; ti4 = ti3;
                                if (v > tv2) { tv3 = tv2; ti3 = ti2;
                                    if (v > tv1) { tv2 = tv1; ti2 = ti1;
                                        if (v > tv0) { tv1 = tv0; ti1 = ti0; tv0 = v; ti0 = e; }
                                        else          { tv1 = v;  ti1 = e; }
                                    } else { tv2 = v; ti2 = e; }
                                } else { tv3 = v; ti3 = e; }
                            } else { tv4 = v; ti4 = e; }
                        } else { tv5 = v; ti5 = e; }
                    }
                }
            }

            const float w0 = expf(tv0 - m), w1 = expf(tv1 - m), w2 = expf(tv2 - m);
            const float w3 = expf(tv3 - m), w4 = expf(tv4 - m), w5 = expf(tv5 - m);
            const float inv = 1.0f / (w0 + w1 + w2 + w3 + w4 + w5 + 1e-20f);

            float* outIdx = out;
            float* outW   = out + (size_t)T * TOPK;
            const size_t base = (size_t)t * TOPK;
            outIdx[base + 0] = (float)ti0;  outW[base + 0] = w0 * inv;
            outIdx[base + 1] = (float)ti1;  outW[base + 1] = w1 * inv;
            outIdx[base + 2] = (float)ti2;  outW[base + 2] = w2 * inv;
            outIdx[base + 3] = (float)ti3;  outW[base + 3] = w3 * inv;
            outIdx[base + 4] = (float)ti4;  outW[base + 4] = w4 * inv;
            outIdx[base + 5] = (float)ti5;  outW[base + 5] = w5 * inv;
        }
    }
}

extern "C" void kernel_launch(void* const* d_in, const int* in_sizes, int n_in,
                              void* d_out, int out_size)
{
    const float* X = (const float*)d_in[0];
    const float* W = (const float*)d_in[1];
    const int T = in_sizes[0] / HIDDEN;   // 16384

    cudaFuncSetAttribute(moe_gate_kernel,
                         cudaFuncAttributeMaxDynamicSharedMemorySize, SMEM_BYTES);

    const int grid = (T + BM - 1) / BM;   // 128
    moe_gate_kernel<<<grid, NTHREADS, SMEM_BYTES>>>(X, W, (float*)d_out, T);
}